// round 17
// baseline (speedup 1.0000x reference)
#include <cuda_runtime.h>
#include <cuda_bf16.h>
#include <cstdint>

// y[m, i2*32+i1] = sum_{j2,j1} x[m,j2*32+j1] * W2[i2,j2] * W1[i1,j1] + bias
// Stage1: T = X @ W1^T (sigma k-permuted A-frags from gmem; W1^T hi-frags
//         in regs, W1^T lo-frags reloaded per row from smem)
// Stage2: G = W2 @ T   (W2 hi-frags in regs, lo reloaded; T via movmatrix)
// R17: R16 (dynamic stealing, 96 regs, 5 CTAs/SM) with the counter reset
// done by a graph memset node instead of a kernel launch, and CHUNK=4 to
// halve the single-address atomics.
// mma.sync.m16n8k16 bf16, fp32 accuracy via 3-term hi/lo split.

typedef unsigned int u32;

#define RS 80                 // weight staging row stride (bytes)
#define NW 4                  // warps per CTA
#define CHUNK 4               // rows per steal

__device__ u32 g_row_ctr;

__shared__ __align__(16) char swts[10240];     // W1h@0 W1l@2560 W2h@5120 W2l@7680
__shared__ __align__(16) float4 pbias4[256];   // [t][lane] tau/frag-permuted bias

__device__ __forceinline__ u32 smem_u32(const void* p) {
    u32 a;
    asm("{ .reg .u64 t; cvta.to.shared.u64 t, %1; cvt.u32.u64 %0, t; }"
        : "=r"(a) : "l"(p));
    return a;
}
__device__ __forceinline__ void ldm_x4(u32* r, u32 addr) {
    asm volatile("ldmatrix.sync.aligned.m8n8.x4.shared.b16 {%0,%1,%2,%3}, [%4];"
                 : "=r"(r[0]), "=r"(r[1]), "=r"(r[2]), "=r"(r[3]) : "r"(addr));
}
__device__ __forceinline__ u32 movm(u32 v) {
    u32 d;
    asm("movmatrix.sync.aligned.m8n8.trans.b16 %0, %1;" : "=r"(d) : "r"(v));
    return d;
}
__device__ __forceinline__ void mma_bf16(float* c, const u32* a, const u32* b) {
    asm volatile(
        "mma.sync.aligned.m16n8k16.row.col.f32.bf16.bf16.f32 "
        "{%0,%1,%2,%3}, {%4,%5,%6,%7}, {%8,%9}, {%0,%1,%2,%3};"
        : "+f"(c[0]), "+f"(c[1]), "+f"(c[2]), "+f"(c[3])
        : "r"(a[0]), "r"(a[1]), "r"(a[2]), "r"(a[3]), "r"(b[0]), "r"(b[1]));
}
// h = bf16x2(a -> low half, b -> high half); l = residuals
__device__ __forceinline__ void split2(float a, float b, u32& h, u32& l) {
    asm("cvt.rn.bf16x2.f32 %0, %1, %2;" : "=r"(h) : "f"(b), "f"(a));
    float ha = __uint_as_float(h << 16);
    float hb = __uint_as_float(h & 0xFFFF0000u);
    float ra = a - ha, rb = b - hb;
    asm("cvt.rn.bf16x2.f32 %0, %1, %2;" : "=r"(l) : "f"(rb), "f"(ra));
}
// split 32 floats, store hi/lo 64B rows at rowPtr / rowPtr+2560
__device__ __forceinline__ void split_store_row(char* rowPtr, const float* v) {
    u32 hw[16], lw[16];
#pragma unroll
    for (int p = 0; p < 16; p++) split2(v[2 * p], v[2 * p + 1], hw[p], lw[p]);
#pragma unroll
    for (int c = 0; c < 4; c++) {
        *(uint4*)(rowPtr + c * 16) =
            make_uint4(hw[4 * c], hw[4 * c + 1], hw[4 * c + 2], hw[4 * c + 3]);
        *(uint4*)(rowPtr + 2560 + c * 16) =
            make_uint4(lw[4 * c], lw[4 * c + 1], lw[4 * c + 2], lw[4 * c + 3]);
    }
}
// sigma: frag k-pos (within 16-block) -> physical col (within 16-block)
__device__ __forceinline__ int sigma16(int k) {
    return 4 * ((k & 7) >> 1) + 2 * (k >> 3) + (k & 1);
}
// tau: frag n-pos -> physical i1 col (involution, global 0..31)
__device__ __forceinline__ int tau32(int n) {
    return 8 * ((n & 7) >> 1) + 2 * (n >> 3) + (n & 1);
}

__global__ void __launch_bounds__(NW * 32, 5)
kron_mma13_kernel(const float* __restrict__ x,
                  const float* __restrict__ w1,
                  const float* __restrict__ w2,
                  const float* __restrict__ bias,
                  float* __restrict__ out,
                  int rows)
{
    const int tid  = threadIdx.x;
    const int lane = tid & 31;
    const int wrp  = tid >> 5;

    const int lq = lane >> 2;           // frag row within 8-block
    const int lr = lane & 3;            // quad index r

    const u32 laneOff = ((lane & 7) + 8 * ((lane >> 3) & 1)) * RS +
                        ((lane >> 4) << 4);

    // ---- one-time staging (all four weight planes into smem) ----
    if (wrp == 0) {
        // M1[nu][c] = W1[tau(nu)][16*(c>>4)+sigma(c&15)]  (lane = nu)
        float v[32];
        const float* wrow = w1 + tau32(lane) * 32;
#pragma unroll
        for (int c = 0; c < 32; c++)
            v[c] = wrow[16 * (c >> 4) + sigma16(c & 15)];
        split_store_row(swts + 0 + lane * RS, v);
    } else if (wrp == 1) {
        // M2[i2][j2] = W2 row-major
        float v[32];
        const float4* r = (const float4*)(w2 + lane * 32);
#pragma unroll
        for (int q = 0; q < 8; q++) {
            float4 t = r[q];
            v[4*q] = t.x; v[4*q+1] = t.y; v[4*q+2] = t.z; v[4*q+3] = t.w;
        }
        split_store_row(swts + 5120 + lane * RS, v);
    }
    // pbias4[t=mt*4+nt][lane]: physical (row 16mt+lq(+8), col 8*lr+2*nt, +1)
    for (int t = wrp; t < 8; t += NW) {
        int mt = t >> 2, nt = t & 3;
        int row = 16 * mt + lq;
        int col = 8 * lr + 2 * nt;
        pbias4[t * 32 + lane] =
            make_float4(bias[row * 32 + col], bias[row * 32 + col + 1],
                        bias[(row + 8) * 32 + col], bias[(row + 8) * 32 + col + 1]);
    }
    __syncthreads();

    // ---- persistent HI weight fragments only (32 regs) ----
    const u32 s0 = smem_u32(swts);
    u32 w1Bh[2][4][2];                  // [kt][nt][reg]
#pragma unroll
    for (int a = 0; a < 2; a++)
#pragma unroll
        for (int b = 0; b < 2; b++) {
            u32 r[4];
            ldm_x4(r, s0 + 0 + a * (16 * RS) + b * 32 + laneOff);
            w1Bh[b][2*a][0] = r[0]; w1Bh[b][2*a+1][0] = r[1];
            w1Bh[b][2*a][1] = r[2]; w1Bh[b][2*a+1][1] = r[3];
        }
    u32 w2Ah[2][2][4];                  // [mt][kt][4]
#pragma unroll
    for (int mt = 0; mt < 2; mt++)
#pragma unroll
        for (int kt = 0; kt < 2; kt++)
            ldm_x4(w2Ah[mt][kt], s0 + 5120 + mt * (16 * RS) + kt * 32 + laneOff);

    // ---- dynamic work stealing over row chunks ----
    for (;;) {
        u32 base;
        if (lane == 0) base = atomicAdd(&g_row_ctr, (u32)CHUNK);
        base = __shfl_sync(0xFFFFFFFFu, base, 0);
        if (base >= (u32)rows) break;
        int mend = (int)base + CHUNK;
        if (mend > rows) mend = rows;

        for (int m = (int)base; m < mend; m++) {
            const float* xb = x + (size_t)m * 1024;
            float acc[32];
#pragma unroll
            for (int i = 0; i < 32; i++) acc[i] = 0.f;

            // ---- stage 1, kt-blocked (X liveness halved) ----
#pragma unroll
            for (int kt = 0; kt < 2; kt++) {
                float4 u0, u1, u2, u3;
                {
                    int base2 = lq * 32 + 16 * kt + 4 * lr;
                    u0 = *(const float4*)(xb + base2);          // mt=0 rows lq
                    u1 = *(const float4*)(xb + base2 + 256);    // mt=0 rows lq+8
                    u2 = *(const float4*)(xb + base2 + 512);    // mt=1
                    u3 = *(const float4*)(xb + base2 + 768);
                }
                u32 XAh[2][4], XAl[2][4];
                split2(u0.x, u0.y, XAh[0][0], XAl[0][0]);
                split2(u1.x, u1.y, XAh[0][1], XAl[0][1]);
                split2(u0.z, u0.w, XAh[0][2], XAl[0][2]);
                split2(u1.z, u1.w, XAh[0][3], XAl[0][3]);
                split2(u2.x, u2.y, XAh[1][0], XAl[1][0]);
                split2(u3.x, u3.y, XAh[1][1], XAl[1][1]);
                split2(u2.z, u2.w, XAh[1][2], XAl[1][2]);
                split2(u3.z, u3.w, XAh[1][3], XAl[1][3]);

                // pass A: Ah x Bh ; pass C: Al x Bh (persistent w1Bh)
#pragma unroll
                for (int mt = 0; mt < 2; mt++)
#pragma unroll
                    for (int nt = 0; nt < 4; nt++) {
                        float* c = &acc[(mt * 4 + nt) * 4];
                        mma_bf16(c, XAh[mt], w1Bh[kt][nt]);
                        mma_bf16(c, XAl[mt], w1Bh[kt][nt]);
                    }
                // pass B: Ah x Bl (w1 lo frags loaded transiently from smem)
#pragma unroll
                for (int a = 0; a < 2; a++) {
                    u32 r[4];
                    ldm_x4(r, s0 + 2560 + a * (16 * RS) + kt * 32 + laneOff);
                    u32 b0[2] = { r[0], r[2] };   // nt = 2a
                    u32 b1[2] = { r[1], r[3] };   // nt = 2a+1
#pragma unroll
                    for (int mt = 0; mt < 2; mt++) {
                        mma_bf16(&acc[(mt * 4 + 2 * a) * 4],     XAh[mt], b0);
                        mma_bf16(&acc[(mt * 4 + 2 * a + 1) * 4], XAh[mt], b1);
                    }
                }
            }

            // ---- stage 2, kt-blocked; acc halves die into TB frags ----
            float acc2[32];
#pragma unroll
            for (int t = 0; t < 8; t++) {
                float4 b4 = pbias4[t * 32 + lane];
                acc2[t*4+0] = b4.x; acc2[t*4+1] = b4.y;
                acc2[t*4+2] = b4.z; acc2[t*4+3] = b4.w;
            }
#pragma unroll
            for (int kt = 0; kt < 2; kt++) {
                u32 TBh[4][2], TBl[4][2];
#pragma unroll
                for (int nt = 0; nt < 4; nt++) {
                    float* c = &acc[(kt * 4 + nt) * 4];
                    u32 h01, l01, h23, l23;
                    split2(c[0], c[1], h01, l01);
                    split2(c[2], c[3], h23, l23);
                    TBh[nt][0] = movm(h01);
                    TBh[nt][1] = movm(h23);
                    TBl[nt][0] = movm(l01);
                    TBl[nt][1] = movm(l23);
                }
#pragma unroll
                for (int mt = 0; mt < 2; mt++)
#pragma unroll
                    for (int nt = 0; nt < 4; nt++) {
                        float* c = &acc2[(mt * 4 + nt) * 4];
                        mma_bf16(c, w2Ah[mt][kt], TBh[nt]);
                        mma_bf16(c, w2Ah[mt][kt], TBl[nt]);
                    }
#pragma unroll
                for (int mt = 0; mt < 2; mt++) {
                    u32 al[4];
                    ldm_x4(al, s0 + 7680 + mt * (16 * RS) + kt * 32 + laneOff);
#pragma unroll
                    for (int nt = 0; nt < 4; nt++)
                        mma_bf16(&acc2[(mt * 4 + nt) * 4], al, TBh[nt]);
                }
            }

            // ---- store: tau gives each lane 32B contiguous -> STG.128 ----
            float* ob = out + (size_t)m * 1024;
#pragma unroll
            for (int mt = 0; mt < 2; mt++)
#pragma unroll
                for (int h = 0; h < 2; h++) {
                    int base2 = (16 * mt + 8 * h + lq) * 32 + 8 * lr;
                    *(float4*)(ob + base2) =
                        make_float4(acc2[(mt*4+0)*4+2*h], acc2[(mt*4+0)*4+2*h+1],
                                    acc2[(mt*4+1)*4+2*h], acc2[(mt*4+1)*4+2*h+1]);
                    *(float4*)(ob + base2 + 4) =
                        make_float4(acc2[(mt*4+2)*4+2*h], acc2[(mt*4+2)*4+2*h+1],
                                    acc2[(mt*4+3)*4+2*h], acc2[(mt*4+3)*4+2*h+1]);
                }
        }
    }
}

extern "C" void kernel_launch(void* const* d_in, const int* in_sizes, int n_in,
                              void* d_out, int out_size) {
    const float* x    = (const float*)d_in[0];
    const float* w1   = (const float*)d_in[1];
    const float* w2   = (const float*)d_in[2];
    const float* bias = (const float*)d_in[3];
    float* out        = (float*)d_out;

    int rows = in_sizes[0] / 1024;    // 65536

    // Reset steal counter via a memset node (cheaper than a kernel launch;
    // graph-capturable, no allocation).
    void* ctr_ptr = nullptr;
    cudaGetSymbolAddress(&ctr_ptr, g_row_ctr);
    cudaMemsetAsync(ctr_ptr, 0, sizeof(u32));

    int grid = 740;                   // 5 CTAs/SM, one resident wave
    int maxg = (rows + NW - 1) / NW;
    if (grid > maxg) grid = maxg;
    kron_mma13_kernel<<<grid, NW * 32>>>(x, w1, w2, bias, out, rows);
}